// round 15
// baseline (speedup 1.0000x reference)
#include <cuda_runtime.h>
#include <cuda_bf16.h>
#include <math.h>
#include <float.h>
#include <stdint.h>

#define BQ 64
#define DIM 768
#define NKEYS 262144
#define VOCAB 50257
#define KNN 8
#define INV_TEMP 0.1f
#define LAM 0.25f
#define EPSV 1e-10f
#define LOG_EPS (-23.025850929940457f)

#define BM 128                 // keys per CTA
#define KF 32                  // fp32 elems per k-chunk
#define NCH (DIM / KF)         // 24
#define NKB (NKEYS / BM)       // 2048
#define ASTRIDE 40             // bf16 row stride (80 B) -> conflict-free ldmatrix
#define NBUF 3
#define CAND16 16
#define SCST 129               // score smem row stride (floats)

// candidates: [row][kb][8]
__device__ float g_cand_v[(size_t)BQ * NKB * KNN];
__device__ int   g_cand_i[(size_t)BQ * NKB * KNN];
__device__ float g_w[BQ * KNN];
__device__ int   g_tok[BQ * KNN];
#define ECH 8
__device__ float2 g_ms[BQ * ECH];

// ---------------- warp-MMA helpers ----------------
__device__ __forceinline__ void ldsm_x4(uint32_t* r, uint32_t addr) {
    asm volatile("ldmatrix.sync.aligned.m8n8.x4.shared.b16 {%0,%1,%2,%3}, [%4];"
                 : "=r"(r[0]), "=r"(r[1]), "=r"(r[2]), "=r"(r[3]) : "r"(addr));
}
__device__ __forceinline__ void mma_bf16(float* d, const uint32_t* a, const uint32_t* b) {
    asm volatile("mma.sync.aligned.m16n8k16.row.col.f32.bf16.bf16.f32 "
                 "{%0,%1,%2,%3}, {%4,%5,%6,%7}, {%8,%9}, {%0,%1,%2,%3};"
                 : "+f"(d[0]), "+f"(d[1]), "+f"(d[2]), "+f"(d[3])
                 : "r"(a[0]), "r"(a[1]), "r"(a[2]), "r"(a[3]), "r"(b[0]), "r"(b[1]));
}

#define ABYTES (NBUF * BM * ASTRIDE * 2)     // 30720
#define BBYTES (NBUF * BQ * ASTRIDE * 2)     // 15360
#define SCBYTES (BQ * SCST * 4)              // 33024
#define RAWBYTES ((SCBYTES > (ABYTES + BBYTES)) ? SCBYTES : (ABYTES + BBYTES))

// ---------------------------------------------------------------------------
// Kernel A: bf16 tensor-core score GEMM + fused per-CTA per-query top-8.
// 3-buffer pipeline, one __syncthreads per chunk.
// ---------------------------------------------------------------------------
__global__ __launch_bounds__(256) void gemm_mma_kernel(
    const float* __restrict__ Q, const float* __restrict__ Keys)
{
    __shared__ __align__(16) char smem_raw[RAWBYTES];
    __shared__ float k2sm[BM];

    __nv_bfloat16 (*As2)[BM][ASTRIDE] =
        (__nv_bfloat16 (*)[BM][ASTRIDE])(smem_raw);
    __nv_bfloat16 (*Bs2)[BQ][ASTRIDE] =
        (__nv_bfloat16 (*)[BQ][ASTRIDE])(smem_raw + ABYTES);
    float* sc = (float*)smem_raw;            // union: valid after mainloop

    const int tid = threadIdx.x;
    const int wid = tid >> 5, lid = tid & 31;
    const int m0 = blockIdx.x * BM;
    const int warp_m = (wid >> 1) * 32;
    const int warp_n = (wid & 1) * 32;

    const int lrow = tid >> 3;
    const int lc4  = tid & 7;

    float acc[2][4][4];
#pragma unroll
    for (int a = 0; a < 2; a++)
#pragma unroll
        for (int b = 0; b < 4; b++)
#pragma unroll
            for (int e = 0; e < 4; e++) acc[a][b][e] = 0.f;

    float k2acc[4] = {0.f, 0.f, 0.f, 0.f};
    float4 ka[4], qa[2];

    auto load_chunk = [&](int c) {
        const int kc = c * KF;
#pragma unroll
        for (int p = 0; p < 4; p++) {
            int row = lrow + 32 * p;
            ka[p] = *(const float4*)(Keys + (size_t)(m0 + row) * DIM + kc + lc4 * 4);
        }
#pragma unroll
        for (int p = 0; p < 2; p++) {
            int row = lrow + 32 * p;
            qa[p] = *(const float4*)(Q + (size_t)row * DIM + kc + lc4 * 4);
        }
    };
    auto store_chunk = [&](int s) {
#pragma unroll
        for (int p = 0; p < 4; p++) {
            int row = lrow + 32 * p;
            float4 v = ka[p];
            k2acc[p] += v.x * v.x + v.y * v.y + v.z * v.z + v.w * v.w;
            __nv_bfloat162 h0 = __floats2bfloat162_rn(v.x, v.y);
            __nv_bfloat162 h1 = __floats2bfloat162_rn(v.z, v.w);
            uint2 u;
            u.x = *(uint32_t*)&h0; u.y = *(uint32_t*)&h1;
            *(uint2*)&As2[s][row][lc4 * 4] = u;
        }
#pragma unroll
        for (int p = 0; p < 2; p++) {
            int row = lrow + 32 * p;
            float4 v = qa[p];
            __nv_bfloat162 h0 = __floats2bfloat162_rn(2.f * v.x, 2.f * v.y);
            __nv_bfloat162 h1 = __floats2bfloat162_rn(2.f * v.z, 2.f * v.w);
            uint2 u;
            u.x = *(uint32_t*)&h0; u.y = *(uint32_t*)&h1;
            *(uint2*)&Bs2[s][row][lc4 * 4] = u;
        }
    };
    auto compute = [&](int s) {
        uint32_t abase = (uint32_t)__cvta_generic_to_shared(&As2[s][0][0]);
        uint32_t bbase = (uint32_t)__cvta_generic_to_shared(&Bs2[s][0][0]);
        const int j = lid >> 3, r = lid & 7;
#pragma unroll
        for (int ks = 0; ks < 2; ks++) {
            uint32_t af[2][4], bfr[2][4];
#pragma unroll
            for (int mt = 0; mt < 2; mt++) {
                int arow = warp_m + mt * 16 + ((j & 1) << 3) + r;
                int acol = ks * 16 + ((j >> 1) << 3);
                ldsm_x4(af[mt], abase + (uint32_t)(arow * ASTRIDE + acol) * 2);
            }
#pragma unroll
            for (int pn = 0; pn < 2; pn++) {
                int brow = warp_n + pn * 16 + ((j >> 1) << 3) + r;
                int bcol = ks * 16 + ((j & 1) << 3);
                ldsm_x4(bfr[pn], bbase + (uint32_t)(brow * ASTRIDE + bcol) * 2);
            }
#pragma unroll
            for (int mt = 0; mt < 2; mt++)
#pragma unroll
                for (int nt = 0; nt < 4; nt++) {
                    uint32_t b2[2] = { bfr[nt >> 1][(nt & 1) * 2],
                                       bfr[nt >> 1][(nt & 1) * 2 + 1] };
                    mma_bf16(acc[mt][nt], af[mt], b2);
                }
        }
    };

    // prologue: chunk0 -> buf0, chunk1 regs in flight
    load_chunk(0);
    store_chunk(0);
    load_chunk(1);
    __syncthreads();

    for (int c = 0; c < NCH; c++) {
        if (c + 1 < NCH) store_chunk((c + 1) % NBUF);   // regs from prev iter
        if (c + 2 < NCH) load_chunk(c + 2);             // issue next loads
        compute(c % NBUF);
        __syncthreads();
    }

    // reduce ||k||^2
#pragma unroll
    for (int p = 0; p < 4; p++) {
        float v = k2acc[p];
        v += __shfl_xor_sync(0xFFFFFFFFu, v, 1);
        v += __shfl_xor_sync(0xFFFFFFFFu, v, 2);
        v += __shfl_xor_sync(0xFFFFFFFFu, v, 4);
        if ((tid & 7) == 0) k2sm[lrow + 32 * p] = v;
    }
    __syncthreads();

    // scores -> smem [q][m], stride SCST
#pragma unroll
    for (int mt = 0; mt < 2; mt++) {
        int mb = warp_m + mt * 16 + (lid >> 2);
        float k2lo = k2sm[mb], k2hi = k2sm[mb + 8];
#pragma unroll
        for (int nt = 0; nt < 4; nt++) {
            int nn = warp_n + nt * 8 + (lid & 3) * 2;
            sc[nn * SCST + mb]             = acc[mt][nt][0] - k2lo;
            sc[(nn + 1) * SCST + mb]       = acc[mt][nt][1] - k2lo;
            sc[nn * SCST + mb + 8]         = acc[mt][nt][2] - k2hi;
            sc[(nn + 1) * SCST + mb + 8]   = acc[mt][nt][3] - k2hi;
        }
    }
    __syncthreads();

    // per-query top-8: 4 threads per query scan 32 keys each, shfl-merge.
    {
        const int q    = tid >> 2;       // 0..63
        const int part = tid & 3;        // 0..3 (consecutive lanes, same warp)
        const float* row = sc + q * SCST + part * 32;

        float tv[KNN]; int ti[KNN];
#pragma unroll
        for (int j = 0; j < KNN; j++) { tv[j] = -FLT_MAX; ti[j] = -1; }
#pragma unroll 4
        for (int m = 0; m < 32; m++) {
            float v = row[m];
            if (v > tv[0]) {
                tv[0] = v; ti[0] = m0 + part * 32 + m;
#pragma unroll
                for (int j = 0; j < KNN - 1; j++) {
                    if (tv[j] > tv[j + 1]) {
                        float t0 = tv[j]; tv[j] = tv[j+1]; tv[j+1] = t0;
                        int   t1 = ti[j]; ti[j] = ti[j+1]; ti[j+1] = t1;
                    }
                }
            }
        }
        // leader (part==0) merges the other 3 lanes' top-8 via shuffles
#pragma unroll
        for (int src = 1; src < 4; src++) {
#pragma unroll
            for (int j = 0; j < KNN; j++) {
                float v  = __shfl_sync(0xFFFFFFFFu, tv[j], (lid & 28) | src);
                int   ix = __shfl_sync(0xFFFFFFFFu, ti[j], (lid & 28) | src);
                if (part == 0 && v > tv[0]) {
                    tv[0] = v; ti[0] = ix;
#pragma unroll
                    for (int jj = 0; jj < KNN - 1; jj++) {
                        if (tv[jj] > tv[jj + 1]) {
                            float t0 = tv[jj]; tv[jj] = tv[jj+1]; tv[jj+1] = t0;
                            int   t1 = ti[jj]; ti[jj] = ti[jj+1]; ti[jj+1] = t1;
                        }
                    }
                }
            }
        }
        if (part == 0) {
            size_t base = ((size_t)q * NKB + blockIdx.x) * KNN;
#pragma unroll
            for (int j = 0; j < KNN; j++) {
                g_cand_v[base + j] = tv[j];
                g_cand_i[base + j] = ti[j];
            }
        }
    }
}

// ---------------------------------------------------------------------------
// Kernel B: per-row merge of NKB*8 candidates -> top-16 -> exact fp32
// rescore -> top-8 + weights + tokens.  grid BQ, 256 threads.
// ---------------------------------------------------------------------------
__global__ __launch_bounds__(256) void topk_merge(
    const float* __restrict__ Q, const float* __restrict__ Keys,
    const int* __restrict__ values)
{
    const int row = blockIdx.x;
    const int tid = threadIdx.x;
    const int wid = tid >> 5, lid = tid & 31;
    const int NC = NKB * KNN;   // 16384

    float tv[CAND16]; int ti[CAND16];
#pragma unroll
    for (int j = 0; j < CAND16; j++) { tv[j] = -FLT_MAX; ti[j] = -1; }

    const float* cv = g_cand_v + (size_t)row * NC;
    const int*   ci = g_cand_i + (size_t)row * NC;
    for (int i = tid; i < NC; i += 256) {
        float v = cv[i];
        if (v > tv[0]) {
            int idx = ci[i];
            tv[0] = v; ti[0] = idx;
#pragma unroll
            for (int j = 0; j < CAND16 - 1; j++) {
                if (tv[j] > tv[j + 1]) {
                    float t0 = tv[j]; tv[j] = tv[j+1]; tv[j+1] = t0;
                    int   t1 = ti[j]; ti[j] = ti[j+1]; ti[j+1] = t1;
                }
            }
        }
    }

    __shared__ float sv[256];
    __shared__ int   si[256];
    __shared__ float rv[256];
    __shared__ int   rp[256];
    __shared__ int   c16i[CAND16];
    __shared__ float c16s[CAND16];

    int pos = CAND16 - 1;
    sv[tid] = tv[pos]; si[tid] = ti[pos];
    __syncthreads();

    for (int sel = 0; sel < CAND16; sel++) {
        rv[tid] = sv[tid]; rp[tid] = tid;
        __syncthreads();
        for (int s = 128; s > 0; s >>= 1) {
            if (tid < s && rv[tid + s] > rv[tid]) { rv[tid] = rv[tid + s]; rp[tid] = rp[tid + s]; }
            __syncthreads();
        }
        int winner = rp[0];
        if (tid == 0) { c16i[sel] = si[winner]; c16s[sel] = rv[0]; }
        __syncthreads();
        if (tid == winner) {
            pos--;
            if (pos >= 0) { sv[tid] = tv[pos]; si[tid] = ti[pos]; }
            else          { sv[tid] = -FLT_MAX; si[tid] = -1; }
        }
        __syncthreads();
    }

    // exact fp32 rescore
    const float* qp = Q + (size_t)row * DIM;
    for (int c = wid; c < CAND16; c += 8) {
        const float* kp = Keys + (size_t)c16i[c] * DIM;
        float dot = 0.f, kk = 0.f;
        for (int j = lid; j < DIM; j += 32) {
            float kv = kp[j];
            dot = fmaf(qp[j], kv, dot);
            kk  = fmaf(kv, kv, kk);
        }
#pragma unroll
        for (int m = 16; m > 0; m >>= 1) {
            dot += __shfl_xor_sync(0xFFFFFFFFu, dot, m);
            kk  += __shfl_xor_sync(0xFFFFFFFFu, kk, m);
        }
        if (lid == 0) c16s[c] = 2.f * dot - kk;
    }
    __syncthreads();

    if (tid == 0) {
        float s16[CAND16]; int i16[CAND16];
#pragma unroll
        for (int j = 0; j < CAND16; j++) { s16[j] = c16s[j]; i16[j] = c16i[j]; }
        float topv[KNN]; int topi[KNN];
        for (int sel = 0; sel < KNN; sel++) {
            int best = -1;
            for (int j = 0; j < CAND16; j++) {
                if (i16[j] < 0) continue;
                if (best < 0 || s16[j] > s16[best] ||
                    (s16[j] == s16[best] && i16[j] < i16[best])) best = j;
            }
            topv[sel] = s16[best]; topi[sel] = i16[best];
            i16[best] = -1;
        }
        float m = topv[0];
        float e[KNN], sum = 0.f;
#pragma unroll
        for (int j = 0; j < KNN; j++) { e[j] = expf((topv[j] - m) * INV_TEMP); sum += e[j]; }
        float inv = 1.f / sum;
#pragma unroll
        for (int j = 0; j < KNN; j++) {
            g_w[row * KNN + j]   = e[j] * inv;
            g_tok[row * KNN + j] = values[topi[j]];
        }
    }
}

// ---------------------------------------------------------------------------
// Kernel E1: per-(row,chunk) softmax partials. grid (ECH, BQ).
// ---------------------------------------------------------------------------
#define VCH ((VOCAB + ECH - 1) / ECH)

__global__ __launch_bounds__(256) void epi_partials(const float* __restrict__ base)
{
    const int chunk = blockIdx.x;
    const int row   = blockIdx.y;
    const int tid   = threadIdx.x;
    const int start = chunk * VCH;
    const int end   = min(start + VCH, VOCAB);
    const float* br = base + (size_t)row * VOCAB;

    __shared__ float red[256];

    float m = -FLT_MAX;
    for (int i = start + tid; i < end; i += 256) m = fmaxf(m, br[i]);
    red[tid] = m; __syncthreads();
    for (int s = 128; s > 0; s >>= 1) {
        if (tid < s) red[tid] = fmaxf(red[tid], red[tid+s]);
        __syncthreads();
    }
    const float mx = red[0];
    __syncthreads();

    float sacc = 0.f;
    for (int i = start + tid; i < end; i += 256) sacc += expf(br[i] - mx);
    red[tid] = sacc; __syncthreads();
    for (int s = 128; s > 0; s >>= 1) {
        if (tid < s) red[tid] += red[tid+s];
        __syncthreads();
    }
    if (tid == 0) g_ms[row * ECH + chunk] = make_float2(mx, red[0]);
}

// ---------------------------------------------------------------------------
// Kernel E2: bulk write. knn part is a constant except at <=8 token positions
// per row (patched afterwards by epi_patch).
// ---------------------------------------------------------------------------
__global__ __launch_bounds__(256) void epi_write(
    const float* __restrict__ base, float* __restrict__ out)
{
    const int chunk = blockIdx.x;
    const int row   = blockIdx.y;
    const int tid   = threadIdx.x;
    const int start = chunk * VCH;
    const int end   = min(start + VCH, VOCAB);
    const float* br = base + (size_t)row * VOCAB;

    float mx = -FLT_MAX;
#pragma unroll
    for (int c = 0; c < ECH; c++) mx = fmaxf(mx, g_ms[row * ECH + c].x);
    float Z = 0.f;
#pragma unroll
    for (int c = 0; c < ECH; c++) {
        float2 p = g_ms[row * ECH + c];
        Z += p.y * expf(p.x - mx);
    }
    const float invZ = 1.f / Z;
    const float invden = 1.f / (1.f + (float)VOCAB * EPSV);
    const float C0 = LAM * EPSV * invden;   // knn prob term when tp == 0

    float* oi = out + (size_t)row * VOCAB;
    float* ob = out + (size_t)BQ * VOCAB + (size_t)row * VOCAB;
    float* ok = out + (size_t)2 * BQ * VOCAB + (size_t)row * VOCAB;

    for (int i = start + tid; i < end; i += 256) {
        float b  = br[i];
        float sb = expf(b - mx) * invZ;
        oi[i] = logf((1.f - LAM) * sb + C0);
        ob[i] = b;
        ok[i] = LOG_EPS;
    }
}

// ---------------------------------------------------------------------------
// Kernel E3: patch the <=8 token positions per row with exact values.
// grid 1, 64 threads (one per row).
// ---------------------------------------------------------------------------
__global__ __launch_bounds__(64) void epi_patch(
    const float* __restrict__ base, float* __restrict__ out)
{
    const int row = threadIdx.x;

    float mx = -FLT_MAX;
#pragma unroll
    for (int c = 0; c < ECH; c++) mx = fmaxf(mx, g_ms[row * ECH + c].x);
    float Z = 0.f;
#pragma unroll
    for (int c = 0; c < ECH; c++) {
        float2 p = g_ms[row * ECH + c];
        Z += p.y * expf(p.x - mx);
    }
    const float invZ = 1.f / Z;
    const float invden = 1.f / (1.f + (float)VOCAB * EPSV);

    float w[KNN]; int tk[KNN];
#pragma unroll
    for (int j = 0; j < KNN; j++) { w[j] = g_w[row*KNN+j]; tk[j] = g_tok[row*KNN+j]; }

    float* oi = out + (size_t)row * VOCAB;
    float* ok = out + (size_t)2 * BQ * VOCAB + (size_t)row * VOCAB;

#pragma unroll
    for (int j = 0; j < KNN; j++) {
        int t = tk[j];
        float tp = 0.f;
#pragma unroll
        for (int l = 0; l < KNN; l++) tp += (tk[l] == t) ? w[l] : 0.f;
        float b  = base[(size_t)row * VOCAB + t];
        float sb = expf(b - mx) * invZ;
        oi[t] = logf((1.f - LAM) * sb + LAM * (tp + EPSV) * invden);
        ok[t] = logf(tp + EPSV);
    }
}

// ---------------------------------------------------------------------------
extern "C" void kernel_launch(void* const* d_in, const int* in_sizes, int n_in,
                              void* d_out, int out_size)
{
    const float* Q    = (const float*)d_in[0];
    const float* BL   = (const float*)d_in[1];
    const float* Keys = (const float*)d_in[2];
    const int*   Vals = (const int*)d_in[3];
    float* out = (float*)d_out;

    gemm_mma_kernel<<<NKB, 256>>>(Q, Keys);
    topk_merge<<<BQ, 256>>>(Q, Keys, Vals);
    epi_partials<<<dim3(ECH, BQ), 256>>>(BL);
    epi_write<<<dim3(ECH, BQ), 256>>>(BL, out);
    epi_patch<<<1, 64>>>(BL, out);
}

// round 16
// speedup vs baseline: 1.1139x; 1.1139x over previous
#include <cuda_runtime.h>
#include <cuda_bf16.h>
#include <math.h>
#include <float.h>
#include <stdint.h>

#define BQ 64
#define DIM 768
#define NKEYS 262144
#define VOCAB 50257
#define KNN 8
#define INV_TEMP 0.1f
#define LAM 0.25f
#define EPSV 1e-10f
#define LOG_EPS (-23.025850929940457f)

#define BM 128                 // keys per CTA
#define KF 32                  // fp32 elems per k-chunk
#define NCH (DIM / KF)         // 24
#define NKB (NKEYS / BM)       // 2048
#define ASTRIDE 40             // bf16 row stride -> conflict-free ldmatrix
#define CAND16 16
#define TCH 16

// packed bf16 scores: u32 at [(kb*BQ + q)*64 + j] holds (m_lo, m_lo+8),
// m_lo = (j>>3)*16 + (j&7)
__device__ uint32_t g_pk[(size_t)NKB * BQ * 64];        // 33.5 MB
__device__ float g_cand_v[BQ * TCH * KNN];
__device__ int   g_cand_i[BQ * TCH * KNN];
__device__ float g_w[BQ * KNN];
__device__ int   g_tok[BQ * KNN];
#define ECH 16
__device__ float2 g_ms[BQ * ECH];

// ---------------- warp-MMA helpers ----------------
__device__ __forceinline__ void ldsm_x4(uint32_t* r, uint32_t addr) {
    asm volatile("ldmatrix.sync.aligned.m8n8.x4.shared.b16 {%0,%1,%2,%3}, [%4];"
                 : "=r"(r[0]), "=r"(r[1]), "=r"(r[2]), "=r"(r[3]) : "r"(addr));
}
__device__ __forceinline__ void mma_bf16(float* d, const uint32_t* a, const uint32_t* b) {
    asm volatile("mma.sync.aligned.m16n8k16.row.col.f32.bf16.bf16.f32 "
                 "{%0,%1,%2,%3}, {%4,%5,%6,%7}, {%8,%9}, {%0,%1,%2,%3};"
                 : "+f"(d[0]), "+f"(d[1]), "+f"(d[2]), "+f"(d[3])
                 : "r"(a[0]), "r"(a[1]), "r"(a[2]), "r"(a[3]), "r"(b[0]), "r"(b[1]));
}

// ---------------------------------------------------------------------------
// Kernel A: bf16 tensor-core score GEMM (round-10 mainloop), packed bf16 out.
// ---------------------------------------------------------------------------
__global__ __launch_bounds__(256) void gemm_mma_kernel(
    const float* __restrict__ Q, const float* __restrict__ Keys)
{
    __shared__ __nv_bfloat16 As2[2][BM][ASTRIDE];
    __shared__ __nv_bfloat16 Bs2[2][BQ][ASTRIDE];
    __shared__ float k2sm[BM];

    const int tid = threadIdx.x;
    const int wid = tid >> 5, lid = tid & 31;
    const int m0 = blockIdx.x * BM;
    const int warp_m = (wid >> 1) * 32;
    const int warp_n = (wid & 1) * 32;

    const int lrow = tid >> 3;
    const int lc4  = tid & 7;

    float acc[2][4][4];
#pragma unroll
    for (int a = 0; a < 2; a++)
#pragma unroll
        for (int b = 0; b < 4; b++)
#pragma unroll
            for (int e = 0; e < 4; e++) acc[a][b][e] = 0.f;

    float k2acc[4] = {0.f, 0.f, 0.f, 0.f};
    float4 ka[4], qa[2];

    auto load_chunk = [&](int c) {
        const int kc = c * KF;
#pragma unroll
        for (int p = 0; p < 4; p++) {
            int row = lrow + 32 * p;
            ka[p] = *(const float4*)(Keys + (size_t)(m0 + row) * DIM + kc + lc4 * 4);
        }
#pragma unroll
        for (int p = 0; p < 2; p++) {
            int row = lrow + 32 * p;
            qa[p] = *(const float4*)(Q + (size_t)row * DIM + kc + lc4 * 4);
        }
    };
    auto store_chunk = [&](int s) {
#pragma unroll
        for (int p = 0; p < 4; p++) {
            int row = lrow + 32 * p;
            float4 v = ka[p];
            k2acc[p] += v.x * v.x + v.y * v.y + v.z * v.z + v.w * v.w;
            __nv_bfloat162 h0 = __floats2bfloat162_rn(v.x, v.y);
            __nv_bfloat162 h1 = __floats2bfloat162_rn(v.z, v.w);
            uint2 u;
            u.x = *(uint32_t*)&h0; u.y = *(uint32_t*)&h1;
            *(uint2*)&As2[s][row][lc4 * 4] = u;
        }
#pragma unroll
        for (int p = 0; p < 2; p++) {
            int row = lrow + 32 * p;
            float4 v = qa[p];
            __nv_bfloat162 h0 = __floats2bfloat162_rn(2.f * v.x, 2.f * v.y);
            __nv_bfloat162 h1 = __floats2bfloat162_rn(2.f * v.z, 2.f * v.w);
            uint2 u;
            u.x = *(uint32_t*)&h0; u.y = *(uint32_t*)&h1;
            *(uint2*)&Bs2[s][row][lc4 * 4] = u;
        }
    };
    auto compute = [&](int s) {
        uint32_t abase = (uint32_t)__cvta_generic_to_shared(&As2[s][0][0]);
        uint32_t bbase = (uint32_t)__cvta_generic_to_shared(&Bs2[s][0][0]);
        const int j = lid >> 3, r = lid & 7;
#pragma unroll
        for (int ks = 0; ks < 2; ks++) {
            uint32_t af[2][4], bfr[2][4];
#pragma unroll
            for (int mt = 0; mt < 2; mt++) {
                int arow = warp_m + mt * 16 + ((j & 1) << 3) + r;
                int acol = ks * 16 + ((j >> 1) << 3);
                ldsm_x4(af[mt], abase + (uint32_t)(arow * ASTRIDE + acol) * 2);
            }
#pragma unroll
            for (int pn = 0; pn < 2; pn++) {
                int brow = warp_n + pn * 16 + ((j >> 1) << 3) + r;
                int bcol = ks * 16 + ((j & 1) << 3);
                ldsm_x4(bfr[pn], bbase + (uint32_t)(brow * ASTRIDE + bcol) * 2);
            }
#pragma unroll
            for (int mt = 0; mt < 2; mt++)
#pragma unroll
                for (int nt = 0; nt < 4; nt++) {
                    uint32_t b2[2] = { bfr[nt >> 1][(nt & 1) * 2],
                                       bfr[nt >> 1][(nt & 1) * 2 + 1] };
                    mma_bf16(acc[mt][nt], af[mt], b2);
                }
        }
    };

    load_chunk(0);
    store_chunk(0);
    __syncthreads();

    for (int c = 0; c < NCH; c++) {
        const int s = c & 1;
        if (c + 1 < NCH) load_chunk(c + 1);
        compute(s);
        __syncthreads();
        if (c + 1 < NCH) {
            store_chunk(s ^ 1);
            __syncthreads();
        }
    }

    // reduce ||k||^2
#pragma unroll
    for (int p = 0; p < 4; p++) {
        float v = k2acc[p];
        v += __shfl_xor_sync(0xFFFFFFFFu, v, 1);
        v += __shfl_xor_sync(0xFFFFFFFFu, v, 2);
        v += __shfl_xor_sync(0xFFFFFFFFu, v, 4);
        if ((tid & 7) == 0) k2sm[lrow + 32 * p] = v;
    }
    __syncthreads();

    // write packed bf16 scores: u32 (m, m+8) per query
    const size_t obase = (size_t)blockIdx.x * BQ * 64;
#pragma unroll
    for (int mt = 0; mt < 2; mt++) {
        int mb = warp_m + mt * 16 + (lid >> 2);        // m_lo
        int jj = ((mb >> 4) << 3) + (mb & 7);          // u32 slot
        float k2lo = k2sm[mb], k2hi = k2sm[mb + 8];
#pragma unroll
        for (int nt = 0; nt < 4; nt++) {
            int nn = warp_n + nt * 8 + (lid & 3) * 2;
            __nv_bfloat162 p0 = __floats2bfloat162_rn(acc[mt][nt][0] - k2lo,
                                                      acc[mt][nt][2] - k2hi);
            __nv_bfloat162 p1 = __floats2bfloat162_rn(acc[mt][nt][1] - k2lo,
                                                      acc[mt][nt][3] - k2hi);
            g_pk[obase + (size_t)nn * 64 + jj]       = *(uint32_t*)&p0;
            g_pk[obase + (size_t)(nn + 1) * 64 + jj] = *(uint32_t*)&p1;
        }
    }
}

// ---------------------------------------------------------------------------
// Kernel B1: per-(row,chunk) top-8 over packed bf16 scores. grid (TCH, BQ).
// chunk covers 128 key-blocks (16384 keys).
// ---------------------------------------------------------------------------
__global__ __launch_bounds__(256) void topk_stage1(void)
{
    const int ch  = blockIdx.x;
    const int row = blockIdx.y;
    const int tid = threadIdx.x;

    float tv[KNN]; int ti[KNN];
#pragma unroll
    for (int j = 0; j < KNN; j++) { tv[j] = -FLT_MAX; ti[j] = -1; }

    auto insert = [&](float v, int idx) {
        if (v > tv[0]) {
            tv[0] = v; ti[0] = idx;
#pragma unroll
            for (int j = 0; j < KNN - 1; j++) {
                if (tv[j] > tv[j + 1]) {
                    float t0 = tv[j]; tv[j] = tv[j+1]; tv[j+1] = t0;
                    int   t1 = ti[j]; ti[j] = ti[j+1]; ti[j+1] = t1;
                }
            }
        }
    };

    // 128 key-blocks x 16 uint4 each
    for (int i = tid; i < 128 * 16; i += 256) {
        const int kbl = i >> 4, v = i & 15;
        const int kb = ch * 128 + kbl;
        const uint4 u4 = *(const uint4*)(g_pk + ((size_t)kb * BQ + row) * 64 + v * 4);
        const uint32_t us[4] = {u4.x, u4.y, u4.z, u4.w};
#pragma unroll
        for (int t = 0; t < 4; t++) {
            const int jj = v * 4 + t;
            const int mlo = ((jj >> 3) << 4) + (jj & 7);
            const int base = kb * 128 + mlo;
            float flo = __uint_as_float(us[t] << 16);
            float fhi = __uint_as_float(us[t] & 0xFFFF0000u);
            insert(flo, base);
            insert(fhi, base + 8);
        }
    }

    __shared__ float sv[256 * KNN];
    __shared__ int   si[256 * KNN];
#pragma unroll
    for (int j = 0; j < KNN; j++) { sv[tid*KNN+j] = tv[j]; si[tid*KNN+j] = ti[j]; }

    __shared__ float rv[256];
    __shared__ int   rp[256];
    __syncthreads();

    for (int sel = 0; sel < KNN; sel++) {
        float bv = -FLT_MAX; int bp = 0;
#pragma unroll
        for (int j = 0; j < KNN; j++) {
            float v = sv[tid*KNN+j];
            if (v > bv) { bv = v; bp = tid*KNN+j; }
        }
        rv[tid] = bv; rp[tid] = bp;
        __syncthreads();
        for (int s = 128; s > 0; s >>= 1) {
            if (tid < s && rv[tid+s] > rv[tid]) { rv[tid] = rv[tid+s]; rp[tid] = rp[tid+s]; }
            __syncthreads();
        }
        if (tid == 0) {
            int p = rp[0];
            g_cand_v[(row * TCH + ch) * KNN + sel] = sv[p];
            g_cand_i[(row * TCH + ch) * KNN + sel] = si[p];
            sv[p] = -FLT_MAX;
        }
        __syncthreads();
    }
}

// ---------------------------------------------------------------------------
// Kernel B2: merge 128 candidates -> top-16, exact fp32 rescore, top-8.
// ---------------------------------------------------------------------------
__global__ __launch_bounds__(128) void topk_stage2(
    const float* __restrict__ Q, const float* __restrict__ Keys,
    const int* __restrict__ values)
{
    const int row = blockIdx.x;
    const int tid = threadIdx.x;
    const int wid = tid >> 5, lid = tid & 31;

    __shared__ float sv[128];
    __shared__ int   si[128];
    __shared__ float rv[128];
    __shared__ int   rp[128];
    __shared__ int   c16i[CAND16];
    __shared__ float c16s[CAND16];

    sv[tid] = g_cand_v[row * 128 + tid];
    si[tid] = g_cand_i[row * 128 + tid];
    __syncthreads();

    for (int sel = 0; sel < CAND16; sel++) {
        rv[tid] = sv[tid]; rp[tid] = tid;
        __syncthreads();
        for (int s = 64; s > 0; s >>= 1) {
            if (tid < s && rv[tid+s] > rv[tid]) { rv[tid] = rv[tid+s]; rp[tid] = rp[tid+s]; }
            __syncthreads();
        }
        if (tid == 0) {
            int p = rp[0];
            c16i[sel] = si[p];
            sv[p] = -FLT_MAX;
        }
        __syncthreads();
    }

    // exact fp32 rescore (4 warps, 4 candidates each)
    const float* qp = Q + (size_t)row * DIM;
    for (int c = wid; c < CAND16; c += 4) {
        const float* kp = Keys + (size_t)c16i[c] * DIM;
        float dot = 0.f, kk = 0.f;
        for (int j = lid; j < DIM; j += 32) {
            float kv = kp[j];
            dot = fmaf(qp[j], kv, dot);
            kk  = fmaf(kv, kv, kk);
        }
#pragma unroll
        for (int m = 16; m > 0; m >>= 1) {
            dot += __shfl_xor_sync(0xFFFFFFFFu, dot, m);
            kk  += __shfl_xor_sync(0xFFFFFFFFu, kk, m);
        }
        if (lid == 0) c16s[c] = 2.f * dot - kk;
    }
    __syncthreads();

    if (tid == 0) {
        float s16[CAND16]; int i16[CAND16];
#pragma unroll
        for (int j = 0; j < CAND16; j++) { s16[j] = c16s[j]; i16[j] = c16i[j]; }
        float topv[KNN]; int topi[KNN];
        for (int sel = 0; sel < KNN; sel++) {
            int best = -1;
            for (int j = 0; j < CAND16; j++) {
                if (i16[j] < 0) continue;
                if (best < 0 || s16[j] > s16[best] ||
                    (s16[j] == s16[best] && i16[j] < i16[best])) best = j;
            }
            topv[sel] = s16[best]; topi[sel] = i16[best];
            i16[best] = -1;
        }
        float m = topv[0];
        float e[KNN], sum = 0.f;
#pragma unroll
        for (int j = 0; j < KNN; j++) { e[j] = expf((topv[j] - m) * INV_TEMP); sum += e[j]; }
        float inv = 1.f / sum;
#pragma unroll
        for (int j = 0; j < KNN; j++) {
            g_w[row * KNN + j]   = e[j] * inv;
            g_tok[row * KNN + j] = values[topi[j]];
        }
    }
}

// ---------------------------------------------------------------------------
// Kernel E1: per-(row,chunk) softmax partials. grid (ECH, BQ).
// ---------------------------------------------------------------------------
#define VCH ((VOCAB + ECH - 1) / ECH)

__global__ __launch_bounds__(256) void epi_partials(const float* __restrict__ base)
{
    const int chunk = blockIdx.x;
    const int row   = blockIdx.y;
    const int tid   = threadIdx.x;
    const int start = chunk * VCH;
    const int end   = min(start + VCH, VOCAB);
    const float* br = base + (size_t)row * VOCAB;

    __shared__ float red[256];

    float m = -FLT_MAX;
    for (int i = start + tid; i < end; i += 256) m = fmaxf(m, br[i]);
    red[tid] = m; __syncthreads();
    for (int s = 128; s > 0; s >>= 1) {
        if (tid < s) red[tid] = fmaxf(red[tid], red[tid+s]);
        __syncthreads();
    }
    const float mx = red[0];
    __syncthreads();

    float sacc = 0.f;
    for (int i = start + tid; i < end; i += 256) sacc += expf(br[i] - mx);
    red[tid] = sacc; __syncthreads();
    for (int s = 128; s > 0; s >>= 1) {
        if (tid < s) red[tid] += red[tid+s];
        __syncthreads();
    }
    if (tid == 0) g_ms[row * ECH + chunk] = make_float2(mx, red[0]);
}

// ---------------------------------------------------------------------------
// Kernel E2: bulk write (knn part constant; token positions patched later).
// ---------------------------------------------------------------------------
__global__ __launch_bounds__(256) void epi_write(
    const float* __restrict__ base, float* __restrict__ out)
{
    const int chunk = blockIdx.x;
    const int row   = blockIdx.y;
    const int tid   = threadIdx.x;
    const int start = chunk * VCH;
    const int end   = min(start + VCH, VOCAB);
    const float* br = base + (size_t)row * VOCAB;

    float mx = -FLT_MAX;
#pragma unroll
    for (int c = 0; c < ECH; c++) mx = fmaxf(mx, g_ms[row * ECH + c].x);
    float Z = 0.f;
#pragma unroll
    for (int c = 0; c < ECH; c++) {
        float2 p = g_ms[row * ECH + c];
        Z += p.y * expf(p.x - mx);
    }
    const float invZ = 1.f / Z;
    const float invden = 1.f / (1.f + (float)VOCAB * EPSV);
    const float C0 = LAM * EPSV * invden;

    float* oi = out + (size_t)row * VOCAB;
    float* ob = out + (size_t)BQ * VOCAB + (size_t)row * VOCAB;
    float* ok = out + (size_t)2 * BQ * VOCAB + (size_t)row * VOCAB;

    for (int i = start + tid; i < end; i += 256) {
        float b  = br[i];
        float sb = expf(b - mx) * invZ;
        oi[i] = logf((1.f - LAM) * sb + C0);
        ob[i] = b;
        ok[i] = LOG_EPS;
    }
}

// ---------------------------------------------------------------------------
// Kernel E3: patch <=8 token positions per row. grid 1, 64 threads.
// ---------------------------------------------------------------------------
__global__ __launch_bounds__(64) void epi_patch(
    const float* __restrict__ base, float* __restrict__ out)
{
    const int row = threadIdx.x;

    float mx = -FLT_MAX;
#pragma unroll
    for (int c = 0; c < ECH; c++) mx = fmaxf(mx, g_ms[row * ECH + c].x);
    float Z = 0.f;
#pragma unroll
    for (int c = 0; c < ECH; c++) {
        float2 p = g_ms[row * ECH + c];
        Z += p.y * expf(p.x - mx);
    }
    const float invZ = 1.f / Z;
    const float invden = 1.f / (1.f + (float)VOCAB * EPSV);

    float w[KNN]; int tk[KNN];
#pragma unroll
    for (int j = 0; j < KNN; j++) { w[j] = g_w[row*KNN+j]; tk[j] = g_tok[row*KNN+j]; }

    float* oi = out + (size_t)row * VOCAB;
    float* ok = out + (size_t)2 * BQ * VOCAB + (size_t)row * VOCAB;

#pragma unroll
    for (int j = 0; j < KNN; j++) {
        int t = tk[j];
        float tp = 0.f;
#pragma unroll
        for (int l = 0; l < KNN; l++) tp += (tk[l] == t) ? w[l] : 0.f;
        float b  = base[(size_t)row * VOCAB + t];
        float sb = expf(b - mx) * invZ;
        oi[t] = logf((1.f - LAM) * sb + LAM * (tp + EPSV) * invden);
        ok[t] = logf(tp + EPSV);
    }
}

// ---------------------------------------------------------------------------
extern "C" void kernel_launch(void* const* d_in, const int* in_sizes, int n_in,
                              void* d_out, int out_size)
{
    const float* Q    = (const float*)d_in[0];
    const float* BL   = (const float*)d_in[1];
    const float* Keys = (const float*)d_in[2];
    const int*   Vals = (const int*)d_in[3];
    float* out = (float*)d_out;

    gemm_mma_kernel<<<NKB, 256>>>(Q, Keys);
    topk_stage1<<<dim3(TCH, BQ), 256>>>();
    topk_stage2<<<BQ, 128>>>(Q, Keys, Vals);
    epi_partials<<<dim3(ECH, BQ), 256>>>(BL);
    epi_write<<<dim3(ECH, BQ), 256>>>(BL, out);
    epi_patch<<<1, 64>>>(BL, out);
}